// round 1
// baseline (speedup 1.0000x reference)
#include <cuda_runtime.h>
#include <math.h>

// ---------------------------------------------------------------------------
// GateAttentionLayer: B=8, L=2048, D=1024, QK=128, UV=2048
//   qk  = gelu(queries @ Wqk + bqk)
//   q,k = rope(qk*gq+betq), rope(qk*gk+betk)
//   v   = gelu(values @ Wv + bv);  ug = gelu(u @ Wu + bu)
//   attn= softmax(q @ k^T / sqrt(QK))
//   o   = (ug * (attn @ v)) @ Wo + bo
// Outputs: concat(o [B*L*D], attn [B*L*L]) as fp32.
// ---------------------------------------------------------------------------

namespace {
constexpr int Bb = 8, Ll = 2048, Dd = 1024, QKd = 128, UVd = 2048;
constexpr long long O_ELEMS    = (long long)Bb * Ll * Dd;   // 16777216
constexpr long long ATTN_ELEMS = (long long)Bb * Ll * Ll;   // 33554432
}

// Scratch (allocation-free rule: static __device__ arrays)
__device__ float g_qk   [Bb * Ll * QKd];
__device__ float g_q    [Bb * Ll * QKd];
__device__ float g_k    [Bb * Ll * QKd];
__device__ float g_v    [Bb * Ll * UVd];
__device__ float g_ug   [Bb * Ll * UVd];
__device__ float g_gated[Bb * Ll * UVd];
__device__ float g_attn [Bb * Ll * Ll];

__device__ __forceinline__ float gelu_tanh(float x) {
    // jax.nn.gelu default (approximate=True)
    float x3 = x * x * x;
    float t  = tanhf(0.7978845608028654f * (x + 0.044715f * x3));
    return 0.5f * x * (1.0f + t);
}

// ---------------------------------------------------------------------------
// Tiled SGEMM: C[M,N] = A[M,K] @ op(B), all row-major, fp32.
// TRANSB=0: B is [K,N];  TRANSB=1: B is [N,K] (C = A @ B^T).
// All of M,N,K must be multiples of the tile dims (true for every call here).
// EPI: 0 none | 1 gelu(acc+bias[c]) | 2 acc+bias[c] | 3 acc*alpha
//      | 4 acc*gate[r*N+c]
// Batched via blockIdx.z with element strides sA/sB/sC/sG.
// ---------------------------------------------------------------------------
template <int TRANSB, int EPI>
__global__ __launch_bounds__(256, 2) void gemm_tile(
    int M, int N, int K,
    const float* __restrict__ A,  long long sA,
    const float* __restrict__ Bp, long long sB,
    float* __restrict__ C,        long long sC,
    const float* __restrict__ bias,
    const float* __restrict__ gate, long long sG,
    float alpha)
{
    constexpr int BM = 128, BN = 128, BK = 16;
    __shared__ float As[BK][BM];
    __shared__ float Bs[BK][BN];

    const long long bz = blockIdx.z;
    A  += bz * sA;
    Bp += bz * sB;
    C  += bz * sC;
    if (EPI == 4) gate += bz * sG;

    const int tid = threadIdx.x;
    const int tx = tid & 15;        // 0..15 -> 8 cols each
    const int ty = tid >> 4;        // 0..15 -> 8 rows each
    const int rowBase = blockIdx.y * BM;
    const int colBase = blockIdx.x * BN;

    float acc[8][8];
#pragma unroll
    for (int i = 0; i < 8; i++)
#pragma unroll
        for (int j = 0; j < 8; j++) acc[i][j] = 0.0f;

    for (int k0 = 0; k0 < K; k0 += BK) {
        // --- A tile: 128 rows x 16 k, store transposed As[k][m] ---
#pragma unroll
        for (int t = 0; t < 2; t++) {
            int id = tid + t * 256;          // 0..511 float4 slots
            int r  = id >> 2;                // 0..127
            int c4 = (id & 3) << 2;          // 0,4,8,12
            float4 va = *(const float4*)(A + (long long)(rowBase + r) * K + k0 + c4);
            As[c4 + 0][r] = va.x; As[c4 + 1][r] = va.y;
            As[c4 + 2][r] = va.z; As[c4 + 3][r] = va.w;
        }
        // --- B tile: Bs[k][n] ---
        if (TRANSB) {
#pragma unroll
            for (int t = 0; t < 2; t++) {
                int id = tid + t * 256;
                int r  = id >> 2;            // n index 0..127
                int c4 = (id & 3) << 2;      // k offset
                float4 vb = *(const float4*)(Bp + (long long)(colBase + r) * K + k0 + c4);
                Bs[c4 + 0][r] = vb.x; Bs[c4 + 1][r] = vb.y;
                Bs[c4 + 2][r] = vb.z; Bs[c4 + 3][r] = vb.w;
            }
        } else {
#pragma unroll
            for (int t = 0; t < 2; t++) {
                int id = tid + t * 256;
                int r  = id >> 5;            // k row 0..15
                int c4 = (id & 31) << 2;     // n offset 0..124
                float4 vb = *(const float4*)(Bp + (long long)(k0 + r) * N + colBase + c4);
                *(float4*)(&Bs[r][c4]) = vb;
            }
        }
        __syncthreads();

#pragma unroll
        for (int kk = 0; kk < BK; kk++) {
            float a[8], b[8];
#pragma unroll
            for (int i = 0; i < 8; i++) a[i] = As[kk][ty * 8 + i];
#pragma unroll
            for (int j = 0; j < 8; j++) b[j] = Bs[kk][tx * 8 + j];
#pragma unroll
            for (int i = 0; i < 8; i++)
#pragma unroll
                for (int j = 0; j < 8; j++)
                    acc[i][j] = fmaf(a[i], b[j], acc[i][j]);
        }
        __syncthreads();
    }

    // --- epilogue ---
#pragma unroll
    for (int i = 0; i < 8; i++) {
        const int r = rowBase + ty * 8 + i;
#pragma unroll
        for (int j = 0; j < 8; j++) {
            const int c = colBase + tx * 8 + j;
            float vv = acc[i][j];
            if (EPI == 1)      vv = gelu_tanh(vv + bias[c]);
            else if (EPI == 2) vv = vv + bias[c];
            else if (EPI == 3) vv = vv * alpha;
            else if (EPI == 4) vv = vv * gate[(long long)r * N + c];
            C[(long long)r * N + c] = vv;
        }
    }
}

// ---------------------------------------------------------------------------
// RoPE + per-channel affine for q and k. One thread per (row, pair).
// ---------------------------------------------------------------------------
__global__ void rope_kernel(const float* __restrict__ qk,
                            const float* __restrict__ gq, const float* __restrict__ betq,
                            const float* __restrict__ gk, const float* __restrict__ betk,
                            float* __restrict__ qout, float* __restrict__ kout)
{
    const int HALF = QKd / 2;
    int idx = blockIdx.x * blockDim.x + threadIdx.x;
    if (idx >= Bb * Ll * HALF) return;
    int p   = idx % HALF;
    int row = idx / HALF;
    int l   = row % Ll;

    float e    = (float)(2 * p) / (float)QKd;
    float invf = 1.0f / powf(10000.0f, e);
    float ang  = (float)l * invf;
    float s, c;
    sincosf(ang, &s, &c);

    float x1 = qk[row * QKd + 2 * p];
    float x2 = qk[row * QKd + 2 * p + 1];

    float q1 = x1 * gq[2 * p]     + betq[2 * p];
    float q2 = x2 * gq[2 * p + 1] + betq[2 * p + 1];
    qout[row * QKd + 2 * p]     = q1 * c - q2 * s;
    qout[row * QKd + 2 * p + 1] = q1 * s + q2 * c;

    float k1 = x1 * gk[2 * p]     + betk[2 * p];
    float k2 = x2 * gk[2 * p + 1] + betk[2 * p + 1];
    kout[row * QKd + 2 * p]     = k1 * c - k2 * s;
    kout[row * QKd + 2 * p + 1] = k1 * s + k2 * c;
}

// ---------------------------------------------------------------------------
// Row softmax, in place. One block (256 threads) per row of length L.
// ---------------------------------------------------------------------------
__global__ void softmax_kernel(float* __restrict__ attn)
{
    const int row = blockIdx.x;
    float* p = attn + (long long)row * Ll;
    const int tid = threadIdx.x;
    __shared__ float red[256];

    float m = -INFINITY;
    for (int i = tid; i < Ll; i += 256) m = fmaxf(m, p[i]);
    red[tid] = m; __syncthreads();
    for (int s = 128; s > 0; s >>= 1) {
        if (tid < s) red[tid] = fmaxf(red[tid], red[tid + s]);
        __syncthreads();
    }
    m = red[0]; __syncthreads();

    float sum = 0.0f;
    for (int i = tid; i < Ll; i += 256) {
        float e = expf(p[i] - m);
        p[i] = e;
        sum += e;
    }
    red[tid] = sum; __syncthreads();
    for (int s = 128; s > 0; s >>= 1) {
        if (tid < s) red[tid] += red[tid + s];
        __syncthreads();
    }
    float r = 1.0f / red[0];
    for (int i = tid; i < Ll; i += 256) p[i] *= r;
}

// ---------------------------------------------------------------------------
extern "C" void kernel_launch(void* const* d_in, const int* in_sizes, int n_in,
                              void* d_out, int out_size)
{
    const float* u       = (const float*)d_in[0];
    const float* queries = (const float*)d_in[1];
    // d_in[2] = keys (unused by the reference graph)
    const float* values  = (const float*)d_in[3];
    const float* Wqk  = (const float*)d_in[4];
    const float* bqk  = (const float*)d_in[5];
    const float* gq   = (const float*)d_in[6];
    const float* betq = (const float*)d_in[7];
    const float* gk   = (const float*)d_in[8];
    const float* betk = (const float*)d_in[9];
    const float* Wv   = (const float*)d_in[10];
    const float* bv   = (const float*)d_in[11];
    const float* Wu   = (const float*)d_in[12];
    const float* bu   = (const float*)d_in[13];
    const float* Wo   = (const float*)d_in[14];
    const float* bo   = (const float*)d_in[15];

    float *qk, *q, *k, *v, *ug, *gated, *attn_s;
    cudaGetSymbolAddress((void**)&qk,    g_qk);
    cudaGetSymbolAddress((void**)&q,     g_q);
    cudaGetSymbolAddress((void**)&k,     g_k);
    cudaGetSymbolAddress((void**)&v,     g_v);
    cudaGetSymbolAddress((void**)&ug,    g_ug);
    cudaGetSymbolAddress((void**)&gated, g_gated);
    cudaGetSymbolAddress((void**)&attn_s, g_attn);

    float* o_out = (float*)d_out;
    // Tuple output flattens as (o, attn); fall back to scratch if the harness
    // only sized d_out for o.
    float* attn = ((long long)out_size >= O_ELEMS + ATTN_ELEMS)
                      ? (o_out + O_ELEMS) : attn_s;

    const int MT = Bb * Ll;                  // 16384 rows
    const dim3 blk(256);
    const long long sQK = (long long)Ll * QKd;
    const long long sAT = (long long)Ll * Ll;
    const long long sUV = (long long)Ll * UVd;

    // 1) qk = gelu(queries @ Wqk + bqk)              [16384 x 128]
    gemm_tile<0, 1><<<dim3(QKd / 128, MT / 128, 1), blk>>>(
        MT, QKd, Dd, queries, 0, Wqk, 0, qk, 0, bqk, nullptr, 0, 0.f);

    // 2) q,k = rope(affine(qk))
    rope_kernel<<<(MT * (QKd / 2) + 255) / 256, 256>>>(qk, gq, betq, gk, betk, q, k);

    // 3) v = gelu(values @ Wv + bv)                  [16384 x 2048]
    gemm_tile<0, 1><<<dim3(UVd / 128, MT / 128, 1), blk>>>(
        MT, UVd, Dd, values, 0, Wv, 0, v, 0, bv, nullptr, 0, 0.f);

    // 4) ug = gelu(u @ Wu + bu)                      [16384 x 2048]
    gemm_tile<0, 1><<<dim3(UVd / 128, MT / 128, 1), blk>>>(
        MT, UVd, Dd, u, 0, Wu, 0, ug, 0, bu, nullptr, 0, 0.f);

    // 5) scores = q @ k^T / sqrt(128)   (batched, B^T path)   [8 x 2048 x 2048]
    gemm_tile<1, 3><<<dim3(Ll / 128, Ll / 128, Bb), blk>>>(
        Ll, Ll, QKd, q, sQK, k, sQK, attn, sAT,
        nullptr, nullptr, 0, 0.08838834764831845f);

    // 6) softmax rows in place
    softmax_kernel<<<MT, 256>>>(attn);

    // 7) gated = ug * (attn @ v)   (batched)          [8 x 2048 x 2048]
    gemm_tile<0, 4><<<dim3(UVd / 128, Ll / 128, Bb), blk>>>(
        Ll, UVd, Ll, attn, sAT, v, sUV, gated, sUV,
        nullptr, ug, sUV, 0.f);

    // 8) o = gated @ Wo + bo                          [16384 x 1024]
    gemm_tile<0, 2><<<dim3(Dd / 128, MT / 128, 1), blk>>>(
        MT, Dd, UVd, gated, 0, Wo, 0, o_out, 0, bo, nullptr, 0, 0.f);
}

// round 2
// speedup vs baseline: 1.5174x; 1.5174x over previous
#include <cuda_runtime.h>
#include <cuda_bf16.h>
#include <math.h>

// ---------------------------------------------------------------------------
// GateAttentionLayer: B=8, L=2048, D=1024, QK=128, UV=2048
// Split-precision bf16 tensor-core GEMMs (hi/lo decomposition, 3 MMAs):
//   x = hi + lo (bf16 each)  =>  x*y ~= hi*hy + hi*ly + lo*hy   (err ~2^-16)
// ---------------------------------------------------------------------------

namespace {
constexpr int Bb = 8, Ll = 2048, Dd = 1024, QKd = 128, UVd = 2048;
constexpr long long O_ELEMS    = (long long)Bb * Ll * Dd;
constexpr long long ATTN_ELEMS = (long long)Bb * Ll * Ll;
}

// Scratch (allocation-free rule: static __device__ arrays)
__device__ float g_qk   [Bb * Ll * QKd];
__device__ float g_q    [Bb * Ll * QKd];
__device__ float g_k    [Bb * Ll * QKd];
__device__ float g_v    [Bb * Ll * UVd];
__device__ float g_ug   [Bb * Ll * UVd];
__device__ float g_gated[Bb * Ll * UVd];
__device__ float g_attn [Bb * Ll * Ll];

__device__ __forceinline__ float gelu_tanh(float x) {
    float x3 = x * x * x;
    float t  = tanhf(0.7978845608028654f * (x + 0.044715f * x3));
    return 0.5f * x * (1.0f + t);
}

__device__ __forceinline__ void split_pair(float x, float y,
                                           unsigned int& hi, unsigned int& lo) {
    __nv_bfloat16 hx = __float2bfloat16(x);
    __nv_bfloat16 hy = __float2bfloat16(y);
    float rx = x - __bfloat162float(hx);
    float ry = y - __bfloat162float(hy);
    __nv_bfloat162 h = __halves2bfloat162(hx, hy);
    __nv_bfloat162 l = __halves2bfloat162(__float2bfloat16(rx), __float2bfloat16(ry));
    hi = *reinterpret_cast<unsigned int*>(&h);
    lo = *reinterpret_cast<unsigned int*>(&l);
}

__device__ __forceinline__ void mma16816(float* c, const unsigned int* a,
                                         const unsigned int* b) {
    asm volatile(
        "mma.sync.aligned.m16n8k16.row.col.f32.bf16.bf16.f32 "
        "{%0,%1,%2,%3}, {%4,%5,%6,%7}, {%8,%9}, {%0,%1,%2,%3};"
        : "+f"(c[0]), "+f"(c[1]), "+f"(c[2]), "+f"(c[3])
        : "r"(a[0]), "r"(a[1]), "r"(a[2]), "r"(a[3]), "r"(b[0]), "r"(b[1]));
}

// ---------------------------------------------------------------------------
// Tensor-core split-bf16 GEMM: C[M,N] = A[M,K] @ op(B), row-major fp32 I/O.
// TRANSB=0: B is [K,N];  TRANSB=1: B is [N,K] (C = A @ B^T).
// M,N multiples of 128; K multiple of 32 (true for every call here).
// EPI: 1 gelu(acc+bias[c]) | 2 acc+bias[c] | 3 acc*alpha | 4 acc*gate[r,c]
// ---------------------------------------------------------------------------
template <int TRANSB, int EPI>
__global__ __launch_bounds__(256, 1) void gemm_mma(
    int M, int N, int K,
    const float* __restrict__ A,  long long sA,
    const float* __restrict__ Bp, long long sB,
    float* __restrict__ C,        long long sC,
    const float* __restrict__ bias,
    const float* __restrict__ gate, long long sG,
    float alpha)
{
    constexpr int BM = 128, BN = 128, BK = 32;
    constexpr int LDS = 20;                 // uint32 (bf16x2) row stride, padded
    __shared__ unsigned int As_hi[BM][LDS];
    __shared__ unsigned int As_lo[BM][LDS];
    __shared__ unsigned int Bs_hi[BN][LDS];
    __shared__ unsigned int Bs_lo[BN][LDS];

    const long long bz = blockIdx.z;
    A  += bz * sA;
    Bp += bz * sB;
    C  += bz * sC;
    if (EPI == 4) gate += bz * sG;

    const int tid  = threadIdx.x;
    const int wid  = tid >> 5;
    const int lane = tid & 31;
    const int g    = lane >> 2;             // 0..7
    const int tg   = lane & 3;              // 0..3
    const int wm   = wid >> 2;              // 0..1  -> 64-row slab
    const int wn   = wid & 3;               // 0..3  -> 32-col slab
    const int rowBase = blockIdx.y * BM;
    const int colBase = blockIdx.x * BN;

    float acc[4][4][4];
#pragma unroll
    for (int i = 0; i < 4; i++)
#pragma unroll
        for (int j = 0; j < 4; j++)
#pragma unroll
            for (int e = 0; e < 4; e++) acc[i][j][e] = 0.0f;

    for (int k0 = 0; k0 < K; k0 += BK) {
        // ---- A tile: 128 x 32 fp32 -> hi/lo bf16x2, layout As[m][k/2] ----
#pragma unroll
        for (int t = 0; t < 4; t++) {
            int id = tid + t * 256;         // 1024 float4 slots
            int r  = id >> 3;               // 0..127
            int c4 = (id & 7) << 2;         // 0,4,...,28
            float4 va = *(const float4*)(A + (long long)(rowBase + r) * K + k0 + c4);
            unsigned int h0, l0, h1, l1;
            split_pair(va.x, va.y, h0, l0);
            split_pair(va.z, va.w, h1, l1);
            As_hi[r][(c4 >> 1) + 0] = h0;  As_hi[r][(c4 >> 1) + 1] = h1;
            As_lo[r][(c4 >> 1) + 0] = l0;  As_lo[r][(c4 >> 1) + 1] = l1;
        }
        // ---- B tile -> hi/lo, layout Bs[n][k/2] (n-major) ----
        if (TRANSB) {
#pragma unroll
            for (int t = 0; t < 4; t++) {
                int id = tid + t * 256;
                int r  = id >> 3;           // n 0..127
                int c4 = (id & 7) << 2;     // k offset
                float4 vb = *(const float4*)(Bp + (long long)(colBase + r) * K + k0 + c4);
                unsigned int h0, l0, h1, l1;
                split_pair(vb.x, vb.y, h0, l0);
                split_pair(vb.z, vb.w, h1, l1);
                Bs_hi[r][(c4 >> 1) + 0] = h0;  Bs_hi[r][(c4 >> 1) + 1] = h1;
                Bs_lo[r][(c4 >> 1) + 0] = l0;  Bs_lo[r][(c4 >> 1) + 1] = l1;
            }
        } else {
            // B is [K,N]: scalar loads (coalesced along n), 16-bit smem scatter
            __nv_bfloat16* bh = (__nv_bfloat16*)&Bs_hi[0][0];
            __nv_bfloat16* bl = (__nv_bfloat16*)&Bs_lo[0][0];
#pragma unroll
            for (int t = 0; t < 16; t++) {
                int id = tid + t * 256;     // 4096 elems
                int kk = id >> 7;           // 0..31
                int cn = id & 127;          // 0..127
                float x = Bp[(long long)(k0 + kk) * N + colBase + cn];
                __nv_bfloat16 hx = __float2bfloat16(x);
                float rx = x - __bfloat162float(hx);
                bh[cn * (2 * LDS) + kk] = hx;
                bl[cn * (2 * LDS) + kk] = __float2bfloat16(rx);
            }
        }
        __syncthreads();

#pragma unroll
        for (int ks = 0; ks < 2; ks++) {
            const int kb = ks * 8;          // pair-index base for this k16 step
            unsigned int ah[4][4], al[4][4], bh[4][2], bl[4][2];
#pragma unroll
            for (int i = 0; i < 4; i++) {
                int r = wm * 64 + i * 16 + g;
                ah[i][0] = As_hi[r][kb + tg];      ah[i][1] = As_hi[r + 8][kb + tg];
                ah[i][2] = As_hi[r][kb + tg + 4];  ah[i][3] = As_hi[r + 8][kb + tg + 4];
                al[i][0] = As_lo[r][kb + tg];      al[i][1] = As_lo[r + 8][kb + tg];
                al[i][2] = As_lo[r][kb + tg + 4];  al[i][3] = As_lo[r + 8][kb + tg + 4];
            }
#pragma unroll
            for (int j = 0; j < 4; j++) {
                int c = wn * 32 + j * 8 + g;
                bh[j][0] = Bs_hi[c][kb + tg];  bh[j][1] = Bs_hi[c][kb + tg + 4];
                bl[j][0] = Bs_lo[c][kb + tg];  bl[j][1] = Bs_lo[c][kb + tg + 4];
            }
#pragma unroll
            for (int i = 0; i < 4; i++)
#pragma unroll
                for (int j = 0; j < 4; j++) {
                    mma16816(acc[i][j], ah[i], bh[j]);
                    mma16816(acc[i][j], ah[i], bl[j]);
                    mma16816(acc[i][j], al[i], bh[j]);
                }
        }
        __syncthreads();
    }

    // ---- epilogue ----
#pragma unroll
    for (int i = 0; i < 4; i++) {
#pragma unroll
        for (int j = 0; j < 4; j++) {
            int r0 = rowBase + wm * 64 + i * 16 + g;
            int c0 = colBase + wn * 32 + j * 8 + tg * 2;
#pragma unroll
            for (int h = 0; h < 2; h++) {
                int r = r0 + h * 8;
                float v0 = acc[i][j][2 * h + 0];
                float v1 = acc[i][j][2 * h + 1];
                if (EPI == 1) {
                    v0 = gelu_tanh(v0 + bias[c0]);
                    v1 = gelu_tanh(v1 + bias[c0 + 1]);
                } else if (EPI == 2) {
                    v0 += bias[c0]; v1 += bias[c0 + 1];
                } else if (EPI == 3) {
                    v0 *= alpha; v1 *= alpha;
                } else if (EPI == 4) {
                    const float2 gg = *(const float2*)(gate + (long long)r * N + c0);
                    v0 *= gg.x; v1 *= gg.y;
                }
                *(float2*)(C + (long long)r * N + c0) = make_float2(v0, v1);
            }
        }
    }
}

// ---------------------------------------------------------------------------
// RoPE + per-channel affine for q and k.
// ---------------------------------------------------------------------------
__global__ void rope_kernel(const float* __restrict__ qk,
                            const float* __restrict__ gq, const float* __restrict__ betq,
                            const float* __restrict__ gk, const float* __restrict__ betk,
                            float* __restrict__ qout, float* __restrict__ kout)
{
    const int HALF = QKd / 2;
    int idx = blockIdx.x * blockDim.x + threadIdx.x;
    if (idx >= Bb * Ll * HALF) return;
    int p   = idx % HALF;
    int row = idx / HALF;
    int l   = row % Ll;

    float e    = (float)(2 * p) / (float)QKd;
    float invf = 1.0f / powf(10000.0f, e);
    float ang  = (float)l * invf;
    float s, c;
    sincosf(ang, &s, &c);

    float x1 = qk[row * QKd + 2 * p];
    float x2 = qk[row * QKd + 2 * p + 1];

    float q1 = x1 * gq[2 * p]     + betq[2 * p];
    float q2 = x2 * gq[2 * p + 1] + betq[2 * p + 1];
    qout[row * QKd + 2 * p]     = q1 * c - q2 * s;
    qout[row * QKd + 2 * p + 1] = q1 * s + q2 * c;

    float k1 = x1 * gk[2 * p]     + betk[2 * p];
    float k2 = x2 * gk[2 * p + 1] + betk[2 * p + 1];
    kout[row * QKd + 2 * p]     = k1 * c - k2 * s;
    kout[row * QKd + 2 * p + 1] = k1 * s + k2 * c;
}

// ---------------------------------------------------------------------------
// Row softmax, in place. One block (256 threads) per row of length L.
// ---------------------------------------------------------------------------
__global__ void softmax_kernel(float* __restrict__ attn)
{
    const int row = blockIdx.x;
    float* p = attn + (long long)row * Ll;
    const int tid = threadIdx.x;
    __shared__ float red[256];

    float m = -INFINITY;
    for (int i = tid; i < Ll; i += 256) m = fmaxf(m, p[i]);
    red[tid] = m; __syncthreads();
    for (int s = 128; s > 0; s >>= 1) {
        if (tid < s) red[tid] = fmaxf(red[tid], red[tid + s]);
        __syncthreads();
    }
    m = red[0]; __syncthreads();

    float sum = 0.0f;
    for (int i = tid; i < Ll; i += 256) {
        float e = expf(p[i] - m);
        p[i] = e;
        sum += e;
    }
    red[tid] = sum; __syncthreads();
    for (int s = 128; s > 0; s >>= 1) {
        if (tid < s) red[tid] += red[tid + s];
        __syncthreads();
    }
    float r = 1.0f / red[0];
    for (int i = tid; i < Ll; i += 256) p[i] *= r;
}

// ---------------------------------------------------------------------------
extern "C" void kernel_launch(void* const* d_in, const int* in_sizes, int n_in,
                              void* d_out, int out_size)
{
    const float* u       = (const float*)d_in[0];
    const float* queries = (const float*)d_in[1];
    // d_in[2] = keys (unused by the reference graph)
    const float* values  = (const float*)d_in[3];
    const float* Wqk  = (const float*)d_in[4];
    const float* bqk  = (const float*)d_in[5];
    const float* gq   = (const float*)d_in[6];
    const float* betq = (const float*)d_in[7];
    const float* gk   = (const float*)d_in[8];
    const float* betk = (const float*)d_in[9];
    const float* Wv   = (const float*)d_in[10];
    const float* bv   = (const float*)d_in[11];
    const float* Wu   = (const float*)d_in[12];
    const float* bu   = (const float*)d_in[13];
    const float* Wo   = (const float*)d_in[14];
    const float* bo   = (const float*)d_in[15];

    float *qk, *q, *k, *v, *ug, *gated, *attn_s;
    cudaGetSymbolAddress((void**)&qk,    g_qk);
    cudaGetSymbolAddress((void**)&q,     g_q);
    cudaGetSymbolAddress((void**)&k,     g_k);
    cudaGetSymbolAddress((void**)&v,     g_v);
    cudaGetSymbolAddress((void**)&ug,    g_ug);
    cudaGetSymbolAddress((void**)&gated, g_gated);
    cudaGetSymbolAddress((void**)&attn_s, g_attn);

    float* o_out = (float*)d_out;
    float* attn = ((long long)out_size >= O_ELEMS + ATTN_ELEMS)
                      ? (o_out + O_ELEMS) : attn_s;

    const int MT = Bb * Ll;                  // 16384 rows
    const dim3 blk(256);
    const long long sQK = (long long)Ll * QKd;
    const long long sAT = (long long)Ll * Ll;
    const long long sUV = (long long)Ll * UVd;

    // 1) qk = gelu(queries @ Wqk + bqk)              [16384 x 128]
    gemm_mma<0, 1><<<dim3(QKd / 128, MT / 128, 1), blk>>>(
        MT, QKd, Dd, queries, 0, Wqk, 0, qk, 0, bqk, nullptr, 0, 0.f);

    // 2) q,k = rope(affine(qk))
    rope_kernel<<<(MT * (QKd / 2) + 255) / 256, 256>>>(qk, gq, betq, gk, betk, q, k);

    // 3) v = gelu(values @ Wv + bv)                  [16384 x 2048]
    gemm_mma<0, 1><<<dim3(UVd / 128, MT / 128, 1), blk>>>(
        MT, UVd, Dd, values, 0, Wv, 0, v, 0, bv, nullptr, 0, 0.f);

    // 4) ug = gelu(u @ Wu + bu)                      [16384 x 2048]
    gemm_mma<0, 1><<<dim3(UVd / 128, MT / 128, 1), blk>>>(
        MT, UVd, Dd, u, 0, Wu, 0, ug, 0, bu, nullptr, 0, 0.f);

    // 5) scores = q @ k^T / sqrt(128)   (batched)    [8 x 2048 x 2048]
    gemm_mma<1, 3><<<dim3(Ll / 128, Ll / 128, Bb), blk>>>(
        Ll, Ll, QKd, q, sQK, k, sQK, attn, sAT,
        nullptr, nullptr, 0, 0.08838834764831845f);

    // 6) softmax rows in place
    softmax_kernel<<<MT, 256>>>(attn);

    // 7) gated = ug * (attn @ v)   (batched)         [8 x 2048 x 2048]
    gemm_mma<0, 4><<<dim3(UVd / 128, Ll / 128, Bb), blk>>>(
        Ll, UVd, Ll, attn, sAT, v, sUV, gated, sUV,
        nullptr, ug, sUV, 0.f);

    // 8) o = gated @ Wo + bo                         [16384 x 1024]
    gemm_mma<0, 2><<<dim3(Dd / 128, MT / 128, 1), blk>>>(
        MT, Dd, UVd, gated, 0, Wo, 0, o_out, 0, bo, nullptr, 0, 0.f);
}

// round 7
// speedup vs baseline: 2.1940x; 1.4459x over previous
#include <cuda_runtime.h>
#include <cuda_bf16.h>
#include <math.h>
#include <stdint.h>

typedef __nv_bfloat16 bf16;

namespace {
constexpr int Bb=8, Ll=2048, Dd=1024, QKd=128, UVd=2048;
constexpr int MT = Bb*Ll;
constexpr long long O_ELEMS = (long long)MT*Dd;
constexpr long long ATTN_ELEMS = (long long)Bb*Ll*Ll;
// smem: 2 stages x 4 planes x [128 rows][20 uint32 (16 pairs + 4 pad)]
constexpr int PLANE_BYTES = 128*20*4;          // 10240
constexpr int STAGE_BYTES = 4*PLANE_BYTES;     // 40960
constexpr int SMEM_BYTES  = 2*STAGE_BYTES;     // 81920
}

// ------------------------- scratch (__device__ globals) --------------------
__device__ __align__(128) float g_qk  [MT*QKd];
__device__ __align__(128) bf16  g_qh[MT*QKd], g_ql[MT*QKd], g_kh[MT*QKd], g_kl[MT*QKd];
__device__ __align__(128) bf16  g_Qh[MT*Dd], g_Ql[MT*Dd], g_Vh[MT*Dd], g_Vl[MT*Dd];
__device__ __align__(128) bf16  g_Uh[MT*Dd], g_Ul[MT*Dd];
__device__ __align__(128) bf16  g_WqkTh[QKd*Dd], g_WqkTl[QKd*Dd];
__device__ __align__(128) bf16  g_WvTh[UVd*Dd],  g_WvTl[UVd*Dd];
__device__ __align__(128) bf16  g_WuTh[UVd*Dd],  g_WuTl[UVd*Dd];
__device__ __align__(128) bf16  g_WoTh[Dd*UVd],  g_WoTl[Dd*UVd];
__device__ __align__(128) bf16  g_vTh[(long long)Bb*UVd*Ll], g_vTl[(long long)Bb*UVd*Ll];
__device__ __align__(128) float g_ug  [(long long)MT*UVd];
__device__ __align__(128) float g_attn[(long long)Bb*Ll*Ll];
__device__ __align__(128) bf16  g_ah[(long long)Bb*Ll*Ll], g_al[(long long)Bb*Ll*Ll];
__device__ __align__(128) bf16  g_gh[(long long)MT*UVd],   g_gl[(long long)MT*UVd];

// ------------------------------ helpers ------------------------------------
__device__ __forceinline__ uint32_t smem_u32(const void* p){
    uint32_t a; asm("{ .reg .u64 t; cvta.to.shared.u64 t, %1; cvt.u32.u64 %0, t; }":"=r"(a):"l"(p)); return a;
}
__device__ __forceinline__ float gelu_f(float x){
    float z = 0.7978845608028654f*(x + 0.044715f*x*x*x);
    float e = __expf(-2.0f*fabsf(z));
    float t = (1.0f-e)/(1.0f+e);
    return 0.5f*x*(1.0f+copysignf(t,z));
}
__device__ __forceinline__ uint32_t pack2(float a, float b){
    __nv_bfloat162 t = __halves2bfloat162(__float2bfloat16(a), __float2bfloat16(b));
    return *reinterpret_cast<uint32_t*>(&t);
}
__device__ __forceinline__ float bf_hi(float x){ return __bfloat162float(__float2bfloat16(x)); }

__device__ __forceinline__ void cp16(uint32_t d, const void* s){
    asm volatile("cp.async.cg.shared.global [%0], [%1], 16;" :: "r"(d), "l"(s));
}
__device__ __forceinline__ void cpcommit(){ asm volatile("cp.async.commit_group;" ::: "memory"); }
template<int N> __device__ __forceinline__ void cpwait(){ asm volatile("cp.async.wait_group %0;"::"n"(N):"memory"); }

__device__ __forceinline__ void mma16816(float* c, const unsigned int* a,
                                         const unsigned int* b) {
    asm volatile(
        "mma.sync.aligned.m16n8k16.row.col.f32.bf16.bf16.f32 "
        "{%0,%1,%2,%3}, {%4,%5,%6,%7}, {%8,%9}, {%0,%1,%2,%3};"
        : "+f"(c[0]), "+f"(c[1]), "+f"(c[2]), "+f"(c[3])
        : "r"(a[0]), "r"(a[1]), "r"(a[2]), "r"(a[3]), "r"(b[0]), "r"(b[1]));
}

// ===========================================================================
// HMMA split-bf16 GEMM: C[M,N] = A @ B^T from pre-split hi/lo bf16 planes.
// A: [M][K] row-major planes; B: [N][K] n-major planes. BK=32, cp.async x2.
// EPI: 0 gelu(acc+bias)->f32 | 1 acc+bias->f32 | 2 acc*alpha->f32
//      3 acc*gate -> hi/lo planes | 4 gelu(acc+bias) -> transposed hi/lo
// ===========================================================================
template<int EPI>
__global__ __launch_bounds__(256,1) void gemm_hmma(
    int K, int N,
    const bf16* __restrict__ Ah, const bf16* __restrict__ Al, long long sA,
    const bf16* __restrict__ Bh, const bf16* __restrict__ Bl, long long sB,
    float* __restrict__ Cf, long long sC,
    bf16* __restrict__ Ch, bf16* __restrict__ Cl, long long sCh,
    const float* __restrict__ bias,
    const float* __restrict__ gate, long long sG, float alpha)
{
    extern __shared__ __align__(16) char smem[];
    const uint32_t sb = smem_u32(smem);

    const int tid  = threadIdx.x;
    const int wid  = tid >> 5;
    const int lane = tid & 31;
    const int g    = lane >> 2;           // 0..7
    const int tg   = lane & 3;            // 0..3
    const int wm   = wid >> 2;            // 0..1 -> 64-row slab
    const int wn   = wid & 3;             // 0..3 -> 32-col slab

    const long long bz = blockIdx.z;
    Ah += bz*sA; Al += bz*sA; Bh += bz*sB; Bl += bz*sB;
    if (EPI<=2) Cf += bz*sC;
    if (EPI==3){ Ch += bz*sCh; Cl += bz*sCh; gate += bz*sG; }
    const int rowBase = blockIdx.y*128, colBase = blockIdx.x*128;

    float acc[4][4][4];
#pragma unroll
    for (int i=0;i<4;i++)
#pragma unroll
        for (int j=0;j<4;j++)
#pragma unroll
            for (int e=0;e<4;e++) acc[i][j][e] = 0.0f;

    const int NC = K >> 5;                // K/32 chunks

    // ---- async stage loader: 4 planes x 128 rows x 64B (as 16B units) ----
    auto load_stage = [&](int kc, int s){
        const uint32_t st = sb + s*STAGE_BYTES;
        const long long k0 = (long long)kc << 5;
#pragma unroll
        for (int t=0;t<8;t++){
            int id    = tid + (t&1)*256;            // 0..511
            int plane = t>>1;                       // 0..3
            int r     = id >> 2;                    // 0..127
            int c16   = id & 3;                     // 16B unit within 64B row
            uint32_t dst = st + plane*PLANE_BYTES + r*80 + c16*16;
            const bf16* src;
            if      (plane==0) src = Ah + (long long)(rowBase+r)*K + k0 + c16*8;
            else if (plane==1) src = Al + (long long)(rowBase+r)*K + k0 + c16*8;
            else if (plane==2) src = Bh + (long long)(colBase+r)*K + k0 + c16*8;
            else               src = Bl + (long long)(colBase+r)*K + k0 + c16*8;
            cp16(dst, src);
        }
        cpcommit();
    };

    load_stage(0, 0);
    if (NC > 1) load_stage(1, 1);
    cpwait<1>();
    __syncthreads();

    for (int c=0; c<NC; c++){
        const int s = c & 1;
        const char* stp = smem + s*STAGE_BYTES;
        const uint32_t* As_hi = (const uint32_t*)(stp);
        const uint32_t* As_lo = (const uint32_t*)(stp +   PLANE_BYTES);
        const uint32_t* Bs_hi = (const uint32_t*)(stp + 2*PLANE_BYTES);
        const uint32_t* Bs_lo = (const uint32_t*)(stp + 3*PLANE_BYTES);

#pragma unroll
        for (int ks=0; ks<2; ks++){
            const int kb = ks*8;
            unsigned int ah[4][4], al[4][4], bh[4][2], bl[4][2];
#pragma unroll
            for (int i=0;i<4;i++){
                int r = wm*64 + i*16 + g;
                ah[i][0] = As_hi[r*20 + kb + tg];       ah[i][1] = As_hi[(r+8)*20 + kb + tg];
                ah[i][2] = As_hi[r*20 + kb + tg + 4];   ah[i][3] = As_hi[(r+8)*20 + kb + tg + 4];
                al[i][0] = As_lo[r*20 + kb + tg];       al[i][1] = As_lo[(r+8)*20 + kb + tg];
                al[i][2] = As_lo[r*20 + kb + tg + 4];   al[i][3] = As_lo[(r+8)*20 + kb + tg + 4];
            }
#pragma unroll
            for (int j=0;j<4;j++){
                int cc = wn*32 + j*8 + g;
                bh[j][0] = Bs_hi[cc*20 + kb + tg];  bh[j][1] = Bs_hi[cc*20 + kb + tg + 4];
                bl[j][0] = Bs_lo[cc*20 + kb + tg];  bl[j][1] = Bs_lo[cc*20 + kb + tg + 4];
            }
#pragma unroll
            for (int i=0;i<4;i++)
#pragma unroll
                for (int j=0;j<4;j++){
                    mma16816(acc[i][j], ah[i], bh[j]);
                    mma16816(acc[i][j], ah[i], bl[j]);
                    mma16816(acc[i][j], al[i], bh[j]);
                }
        }

        if (c+1 < NC){
            __syncthreads();                       // all warps done reading stage s
            if (c+2 < NC){ load_stage(c+2, s); cpwait<1>(); }
            else         { cpwait<0>(); }
            __syncthreads();                       // stage s^1 data visible to all
        }
    }

    // ------------------------------- epilogue ------------------------------
#pragma unroll
    for (int i=0;i<4;i++){
#pragma unroll
        for (int j=0;j<4;j++){
            const int r0 = rowBase + wm*64 + i*16 + g;
            const int c0 = colBase + wn*32 + j*8 + tg*2;
#pragma unroll
            for (int h=0;h<2;h++){
                const int r = r0 + h*8;
                float v0 = acc[i][j][2*h+0];
                float v1 = acc[i][j][2*h+1];
                if (EPI==0){
                    v0 = gelu_f(v0 + bias[c0]);
                    v1 = gelu_f(v1 + bias[c0+1]);
                    *(float2*)(Cf + (long long)r*N + c0) = make_float2(v0, v1);
                } else if (EPI==1){
                    v0 += bias[c0]; v1 += bias[c0+1];
                    *(float2*)(Cf + (long long)r*N + c0) = make_float2(v0, v1);
                } else if (EPI==2){
                    *(float2*)(Cf + (long long)r*N + c0) = make_float2(v0*alpha, v1*alpha);
                } else if (EPI==3){
                    const long long off = (long long)r*N + c0;
                    const float2 gg = *(const float2*)(gate + off);
                    float x0 = v0*gg.x, x1 = v1*gg.y;
                    *(uint32_t*)(Ch + off) = pack2(x0, x1);
                    *(uint32_t*)(Cl + off) = pack2(x0 - bf_hi(x0), x1 - bf_hi(x1));
                } else {  // EPI==4: transposed planes [Bb][UVd][Ll]
                    const int b = r >> 11, l = r & (Ll-1);
                    float x0 = gelu_f(v0 + bias[c0]);
                    float x1 = gelu_f(v1 + bias[c0+1]);
                    long long off0 = ((long long)b*UVd + c0)*Ll + l;
                    Ch[off0]      = __float2bfloat16(x0);
                    Cl[off0]      = __float2bfloat16(x0 - bf_hi(x0));
                    Ch[off0 + Ll] = __float2bfloat16(x1);
                    Cl[off0 + Ll] = __float2bfloat16(x1 - bf_hi(x1));
                }
            }
        }
    }
}

// --------------------------- small kernels ---------------------------------
__global__ void conv_hl(const float4* __restrict__ x, uint2* __restrict__ h,
                        uint2* __restrict__ l, int n4)
{
    int i = blockIdx.x*256 + threadIdx.x;
    if (i >= n4) return;
    float4 v = x[i];
    h[i] = make_uint2(pack2(v.x,v.y), pack2(v.z,v.w));
    l[i] = make_uint2(pack2(v.x-bf_hi(v.x),v.y-bf_hi(v.y)),
                      pack2(v.z-bf_hi(v.z),v.w-bf_hi(v.w)));
}

__global__ void convT_hl(const float* __restrict__ W, bf16* __restrict__ th,
                         bf16* __restrict__ tl, int Rw, int Cw)
{
    __shared__ float t[32][33];
    int rB = blockIdx.y*32, cB = blockIdx.x*32;
    t[threadIdx.y][threadIdx.x] = W[(long long)(rB+threadIdx.y)*Cw + cB + threadIdx.x];
    __syncthreads();
    float v = t[threadIdx.x][threadIdx.y];
    long long o = (long long)(cB+threadIdx.y)*Rw + rB + threadIdx.x;
    th[o] = __float2bfloat16(v);
    tl[o] = __float2bfloat16(v - bf_hi(v));
}

__global__ void rope_hl(const float* __restrict__ qk,
                        const float* __restrict__ gq, const float* __restrict__ betq,
                        const float* __restrict__ gk, const float* __restrict__ betk,
                        bf16* __restrict__ qh, bf16* __restrict__ ql,
                        bf16* __restrict__ kh, bf16* __restrict__ kl)
{
    int idx = blockIdx.x*256 + threadIdx.x;
    if (idx >= MT*64) return;
    int p = idx&63, row = idx>>6, l = row&(Ll-1);
    float invf = powf(10000.0f, -(float)(2*p)/128.0f);
    float s, c; sincosf((float)l*invf, &s, &c);
    float2 v = ((const float2*)qk)[idx];
    float q1 = v.x*gq[2*p]+betq[2*p], q2 = v.y*gq[2*p+1]+betq[2*p+1];
    float a = q1*c-q2*s, b = q1*s+q2*c;
    ((uint32_t*)qh)[idx] = pack2(a,b);
    ((uint32_t*)ql)[idx] = pack2(a-bf_hi(a), b-bf_hi(b));
    float k1 = v.x*gk[2*p]+betk[2*p], k2 = v.y*gk[2*p+1]+betk[2*p+1];
    a = k1*c-k2*s; b = k1*s+k2*c;
    ((uint32_t*)kh)[idx] = pack2(a,b);
    ((uint32_t*)kl)[idx] = pack2(a-bf_hi(a), b-bf_hi(b));
}

__global__ void softmax_hl(float* __restrict__ attn,
                           bf16* __restrict__ ah, bf16* __restrict__ al)
{
    const long long row = blockIdx.x;
    float* p = attn + row*Ll;
    const int tid = threadIdx.x;
    __shared__ float red[256];

    float m = -INFINITY;
    for (int i=tid;i<Ll;i+=256) m = fmaxf(m, p[i]);
    red[tid]=m; __syncthreads();
    for (int s=128;s>0;s>>=1){ if(tid<s) red[tid]=fmaxf(red[tid],red[tid+s]); __syncthreads(); }
    m = red[0]; __syncthreads();

    float sum = 0.0f;
    for (int i=tid;i<Ll;i+=256){ float e=__expf(p[i]-m); p[i]=e; sum+=e; }
    red[tid]=sum; __syncthreads();
    for (int s=128;s>0;s>>=1){ if(tid<s) red[tid]+=red[tid+s]; __syncthreads(); }
    float r = 1.0f/red[0];

    uint32_t* wh = (uint32_t*)ah + row*(Ll/2);
    uint32_t* wl = (uint32_t*)al + row*(Ll/2);
    for (int i=tid;i<Ll/2;i+=256){
        float2 e = ((float2*)p)[i];
        float v0=e.x*r, v1=e.y*r;
        ((float2*)p)[i] = make_float2(v0,v1);
        wh[i] = pack2(v0,v1);
        wl[i] = pack2(v0-bf_hi(v0), v1-bf_hi(v1));
    }
}

// ---------------------------------------------------------------------------
extern "C" void kernel_launch(void* const* d_in, const int* in_sizes, int n_in,
                              void* d_out, int out_size)
{
    const float* u       = (const float*)d_in[0];
    const float* queries = (const float*)d_in[1];
    const float* values  = (const float*)d_in[3];
    const float* Wqk  = (const float*)d_in[4];
    const float* bqk  = (const float*)d_in[5];
    const float* gq   = (const float*)d_in[6];
    const float* betq = (const float*)d_in[7];
    const float* gk   = (const float*)d_in[8];
    const float* betk = (const float*)d_in[9];
    const float* Wv   = (const float*)d_in[10];
    const float* bv   = (const float*)d_in[11];
    const float* Wu   = (const float*)d_in[12];
    const float* bu   = (const float*)d_in[13];
    const float* Wo   = (const float*)d_in[14];
    const float* bo   = (const float*)d_in[15];

    float *qk, *ug, *attn_s;
    bf16 *qh,*ql,*kh,*kl,*Qh,*Ql,*Vh,*Vl,*Uh,*Ul;
    bf16 *WqkTh,*WqkTl,*WvTh,*WvTl,*WuTh,*WuTl,*WoTh,*WoTl;
    bf16 *vTh,*vTl,*ah,*al,*gh,*gl;
    cudaGetSymbolAddress((void**)&qk, g_qk);
    cudaGetSymbolAddress((void**)&qh, g_qh);   cudaGetSymbolAddress((void**)&ql, g_ql);
    cudaGetSymbolAddress((void**)&kh, g_kh);   cudaGetSymbolAddress((void**)&kl, g_kl);
    cudaGetSymbolAddress((void**)&Qh, g_Qh);   cudaGetSymbolAddress((void**)&Ql, g_Ql);
    cudaGetSymbolAddress((void**)&Vh, g_Vh);   cudaGetSymbolAddress((void**)&Vl, g_Vl);
    cudaGetSymbolAddress((void**)&Uh, g_Uh);   cudaGetSymbolAddress((void**)&Ul, g_Ul);
    cudaGetSymbolAddress((void**)&WqkTh, g_WqkTh); cudaGetSymbolAddress((void**)&WqkTl, g_WqkTl);
    cudaGetSymbolAddress((void**)&WvTh, g_WvTh);   cudaGetSymbolAddress((void**)&WvTl, g_WvTl);
    cudaGetSymbolAddress((void**)&WuTh, g_WuTh);   cudaGetSymbolAddress((void**)&WuTl, g_WuTl);
    cudaGetSymbolAddress((void**)&WoTh, g_WoTh);   cudaGetSymbolAddress((void**)&WoTl, g_WoTl);
    cudaGetSymbolAddress((void**)&vTh, g_vTh);     cudaGetSymbolAddress((void**)&vTl, g_vTl);
    cudaGetSymbolAddress((void**)&ug, g_ug);
    cudaGetSymbolAddress((void**)&attn_s, g_attn);
    cudaGetSymbolAddress((void**)&ah, g_ah);   cudaGetSymbolAddress((void**)&al, g_al);
    cudaGetSymbolAddress((void**)&gh, g_gh);   cudaGetSymbolAddress((void**)&gl, g_gl);

    float* o_out = (float*)d_out;
    float* attn = ((long long)out_size >= O_ELEMS + ATTN_ELEMS)
                      ? (o_out + O_ELEMS) : attn_s;

    cudaFuncSetAttribute(gemm_hmma<0>, cudaFuncAttributeMaxDynamicSharedMemorySize, SMEM_BYTES);
    cudaFuncSetAttribute(gemm_hmma<1>, cudaFuncAttributeMaxDynamicSharedMemorySize, SMEM_BYTES);
    cudaFuncSetAttribute(gemm_hmma<2>, cudaFuncAttributeMaxDynamicSharedMemorySize, SMEM_BYTES);
    cudaFuncSetAttribute(gemm_hmma<3>, cudaFuncAttributeMaxDynamicSharedMemorySize, SMEM_BYTES);
    cudaFuncSetAttribute(gemm_hmma<4>, cudaFuncAttributeMaxDynamicSharedMemorySize, SMEM_BYTES);

    const long long sQK = (long long)Ll*QKd, sAT = (long long)Ll*Ll;
    const long long sUV = (long long)Ll*UVd, sVT = (long long)UVd*Ll;
    const int n4 = MT*Dd/4;

    // input + weight conversion to hi/lo planes
    conv_hl<<<(n4+255)/256,256>>>((const float4*)queries,(uint2*)Qh,(uint2*)Ql,n4);
    conv_hl<<<(n4+255)/256,256>>>((const float4*)values, (uint2*)Vh,(uint2*)Vl,n4);
    conv_hl<<<(n4+255)/256,256>>>((const float4*)u,      (uint2*)Uh,(uint2*)Ul,n4);
    convT_hl<<<dim3(QKd/32, Dd/32), dim3(32,32)>>>(Wqk, WqkTh, WqkTl, Dd, QKd);
    convT_hl<<<dim3(UVd/32, Dd/32), dim3(32,32)>>>(Wv,  WvTh,  WvTl,  Dd, UVd);
    convT_hl<<<dim3(UVd/32, Dd/32), dim3(32,32)>>>(Wu,  WuTh,  WuTl,  Dd, UVd);
    convT_hl<<<dim3(Dd/32, UVd/32), dim3(32,32)>>>(Wo,  WoTh,  WoTl,  UVd, Dd);

    // 1) qk = gelu(queries @ Wqk + bqk)            [16384 x 128]
    gemm_hmma<0><<<dim3(1,128,1),256,SMEM_BYTES>>>(Dd, QKd, Qh,Ql,0, WqkTh,WqkTl,0,
        qk,0, nullptr,nullptr,0, bqk, nullptr,0, 0.f);
    // 2) rope -> q/k hi-lo planes
    rope_hl<<<(MT*64+255)/256,256>>>(qk, gq,betq, gk,betk, qh,ql, kh,kl);
    // 3) v^T planes = gelu(values @ Wv + bv)^T     [8][2048][2048]
    gemm_hmma<4><<<dim3(UVd/128,128,1),256,SMEM_BYTES>>>(Dd, UVd, Vh,Vl,0, WvTh,WvTl,0,
        nullptr,0, vTh,vTl,0, bv, nullptr,0, 0.f);
    // 4) ug = gelu(u @ Wu + bu)                    [16384 x 2048] f32
    gemm_hmma<0><<<dim3(UVd/128,128,1),256,SMEM_BYTES>>>(Dd, UVd, Uh,Ul,0, WuTh,WuTl,0,
        ug,0, nullptr,nullptr,0, bu, nullptr,0, 0.f);
    // 5) scores = q @ k^T / sqrt(128)              [8 x 2048 x 2048]
    gemm_hmma<2><<<dim3(Ll/128,Ll/128,Bb),256,SMEM_BYTES>>>(QKd, Ll, qh,ql,sQK, kh,kl,sQK,
        attn,sAT, nullptr,nullptr,0, nullptr, nullptr,0, 0.08838834764831845f);
    // 6) softmax rows -> attn f32 + hi/lo planes
    softmax_hl<<<MT,256>>>(attn, ah, al);
    // 7) gated planes = ug * (attn @ v)            [8 x 2048 x 2048]
    gemm_hmma<3><<<dim3(UVd/128,Ll/128,Bb),256,SMEM_BYTES>>>(Ll, UVd, ah,al,sAT, vTh,vTl,sVT,
        nullptr,0, gh,gl,sUV, nullptr, ug,sUV, 0.f);
    // 8) o = gated @ Wo + bo                       [16384 x 1024]
    gemm_hmma<1><<<dim3(Dd/128,128,1),256,SMEM_BYTES>>>(UVd, Dd, gh,gl,0, WoTh,WoTl,0,
        o_out,0, nullptr,nullptr,0, bo, nullptr,0, 0.f);
}